// round 5
// baseline (speedup 1.0000x reference)
#include <cuda_runtime.h>
#include <math.h>

#define NX 160
#define D  48
#define NW 3
#define N3 (NX*NX*NX)
#define M_TV 159

// Scratch (device globals: allocation-free per harness rules)
__device__ float g_G1[NW*NX*D*D];     // [w][a][q][r]
__device__ float g_G2[NW*NX*NX*D];    // [w][a][b][r]
// PADDED to 4 floats per node: [n][w], w in 0..2, lane 3 = 0 (zero-init, never read)
__device__ float4 g_G3[(size_t)N3];
__device__ double g_tv;

__global__ void k_zero() { g_tv = 0.0; }

// K1: G1[w][a][q][r] = sum_p x[a,p] * W[w,p,q,r]
__global__ void k1(const float* __restrict__ x, const float* __restrict__ W) {
    int blk = blockIdx.x;
    int w = blk / NX, a = blk % NX;
    __shared__ float xs[D];
    int t = threadIdx.x;
    if (t < D) xs[t] = x[a*D + t];
    __syncthreads();
    const float* Wp = W + (size_t)w*D*D*D;  // [p][q*48+r]
    float acc[9];
    #pragma unroll
    for (int j = 0; j < 9; j++) acc[j] = 0.f;
    for (int p = 0; p < D; p++) {
        float xv = xs[p];
        const float* row = Wp + p*(D*D);
        #pragma unroll
        for (int j = 0; j < 9; j++) acc[j] = fmaf(xv, row[t + 256*j], acc[j]);
    }
    float* outp = g_G1 + (size_t)blk*(D*D);
    #pragma unroll
    for (int j = 0; j < 9; j++) outp[t + 256*j] = acc[j];
}

// K2: G2[w][a][b][r] = sum_q y[b,q] * G1[w][a][q][r]
__global__ void k2(const float* __restrict__ y) {
    int blk = blockIdx.x;
    __shared__ float ys[NX][D];
    __shared__ float g1s[D][D];
    int t = threadIdx.x;
    const float* G1p = g_G1 + (size_t)blk*D*D;
    for (int i = t; i < NX*D; i += 256) ys[i/D][i%D] = y[i];
    for (int i = t; i < D*D; i += 256) g1s[i/D][i%D] = G1p[i];
    __syncthreads();
    int tx = t & 15, ty = t >> 4;
    float acc[10][3];
    #pragma unroll
    for (int jb = 0; jb < 10; jb++)
        #pragma unroll
        for (int jr = 0; jr < 3; jr++) acc[jb][jr] = 0.f;
    for (int q = 0; q < D; q++) {
        float yv[10], gv[3];
        #pragma unroll
        for (int jb = 0; jb < 10; jb++) yv[jb] = ys[ty + 16*jb][q];
        #pragma unroll
        for (int jr = 0; jr < 3; jr++) gv[jr] = g1s[q][tx + 16*jr];
        #pragma unroll
        for (int jb = 0; jb < 10; jb++)
            #pragma unroll
            for (int jr = 0; jr < 3; jr++)
                acc[jb][jr] = fmaf(yv[jb], gv[jr], acc[jb][jr]);
    }
    float* outp = g_G2 + (size_t)blk*NX*D;
    #pragma unroll
    for (int jb = 0; jb < 10; jb++)
        #pragma unroll
        for (int jr = 0; jr < 3; jr++)
            outp[(ty + 16*jb)*D + tx + 16*jr] = acc[jb][jr];
}

// K3: g[w,a,b,c] = sum_r G2[w][a][b][r] * z[c,r], stored g_G3[n].{x,y,z}[w]
__global__ void k3(const float* __restrict__ z) {
    int blk = blockIdx.x;
    int half = blk & 1;
    int wa = blk >> 1;
    int w = wa / NX, a = wa % NX;
    __shared__ float zs[NX][D + 1];
    __shared__ float g2s[80][D];
    int t = threadIdx.x;
    for (int i = t; i < NX*D; i += 256) zs[i/D][i%D] = z[i];
    const float* G2p = g_G2 + ((size_t)wa*NX + half*80)*D;
    for (int i = t; i < 80*D; i += 256) g2s[i/D][i%D] = G2p[i];
    __syncthreads();
    int tx = t & 15, ty = t >> 4;
    float acc[5][10];
    #pragma unroll
    for (int jb = 0; jb < 5; jb++)
        #pragma unroll
        for (int jc = 0; jc < 10; jc++) acc[jb][jc] = 0.f;
    for (int r = 0; r < D; r++) {
        float gv[5], zv[10];
        #pragma unroll
        for (int jb = 0; jb < 5; jb++) gv[jb] = g2s[ty + 16*jb][r];
        #pragma unroll
        for (int jc = 0; jc < 10; jc++) zv[jc] = zs[tx + 16*jc][r];
        #pragma unroll
        for (int jb = 0; jb < 5; jb++)
            #pragma unroll
            for (int jc = 0; jc < 10; jc++)
                acc[jb][jc] = fmaf(gv[jb], zv[jc], acc[jb][jc]);
    }
    int b0 = half*80;
    float* G3f = (float*)g_G3;
    #pragma unroll
    for (int jb = 0; jb < 5; jb++) {
        int b = b0 + ty + 16*jb;
        size_t rowbase = ((size_t)(a*NX + b))*NX;
        #pragma unroll
        for (int jc = 0; jc < 10; jc++) {
            int c = tx + 16*jc;
            G3f[(rowbase + c)*4 + w] = acc[jb][jc];
        }
    }
}

// TV: sum over w,a,b,c<159 of sqrt(eps + dc^2 + db^2 + da^2)
// c mapped to lane index -> 4 fully coalesced float4 loads per thread.
__global__ void k_tv() {
    int idx = blockIdx.x*blockDim.x + threadIdx.x;
    float val = 0.f;
    // index space: a in [0,159), b in [0,159), c in [0,160) with c fastest
    if (idx < M_TV*M_TV*NX) {
        int c = idx % NX;
        int tmp = idx / NX;
        int b = tmp % M_TV;
        int a = tmp / M_TV;
        if (c < M_TV) {
            size_t n = ((size_t)a*NX + b)*NX + c;
            float4 v0 = __ldg(&g_G3[n]);
            float4 vc = __ldg(&g_G3[n + 1]);
            float4 vb = __ldg(&g_G3[n + NX]);
            float4 va = __ldg(&g_G3[n + (size_t)NX*NX]);
            float dc, db, da;
            dc = vc.x - v0.x; db = vb.x - v0.x; da = va.x - v0.x;
            val += sqrtf(1e-5f + dc*dc + db*db + da*da);
            dc = vc.y - v0.y; db = vb.y - v0.y; da = va.y - v0.y;
            val += sqrtf(1e-5f + dc*dc + db*db + da*da);
            dc = vc.z - v0.z; db = vb.z - v0.z; da = va.z - v0.z;
            val += sqrtf(1e-5f + dc*dc + db*db + da*da);
        }
    }
    #pragma unroll
    for (int o = 16; o > 0; o >>= 1) val += __shfl_down_sync(0xffffffffu, val, o);
    __shared__ float warp_sums[8];
    int t = threadIdx.x;
    if ((t & 31) == 0) warp_sums[t >> 5] = val;
    __syncthreads();
    if (t == 0) {
        float s = 0.f;
        #pragma unroll
        for (int i = 0; i < 8; i++) s += warp_sums[i];
        atomicAdd(&g_tv, (double)s);
    }
}

__global__ void k_fin(float* __restrict__ out, int pos) {
    double denom = (double)M_TV * M_TV * M_TV;
    out[pos] = (float)(g_tv / denom);  // SCALING = 1.0
}

// Gather: out[i][w] = sum_k B_w[i,k] * g3[B_idx[i,k]].{x,y,z}
// One aligned LDG.128 per tap: exactly 1 L2 sector each.
__global__ void k_gather(const int* __restrict__ B_idx, const float* __restrict__ B_w,
                         float* __restrict__ out, int NP) {
    int i = blockIdx.x*blockDim.x + threadIdx.x;
    if (i >= NP) return;
    const int4*   bi = (const int4*)(B_idx + (size_t)i*8);
    const float4* bw = (const float4*)(B_w + (size_t)i*8);
    int4 i0 = bi[0], i1 = bi[1];
    float4 w0 = bw[0], w1 = bw[1];
    int   idxs[8] = {i0.x, i0.y, i0.z, i0.w, i1.x, i1.y, i1.z, i1.w};
    float ws[8]   = {w0.x, w0.y, w0.z, w0.w, w1.x, w1.y, w1.z, w1.w};
    // issue all 8 independent 16B gathers up front for max MLP
    float4 v[8];
    #pragma unroll
    for (int k = 0; k < 8; k++) v[k] = __ldg(&g_G3[(size_t)idxs[k]]);
    float a0 = 0.f, a1 = 0.f, a2 = 0.f;
    #pragma unroll
    for (int k = 0; k < 8; k++) {
        float wk = ws[k];
        a0 = fmaf(wk, v[k].x, a0);
        a1 = fmaf(wk, v[k].y, a1);
        a2 = fmaf(wk, v[k].z, a2);
    }
    size_t o = (size_t)i*3;
    out[o + 0] = a0;
    out[o + 1] = a1;
    out[o + 2] = a2;
}

extern "C" void kernel_launch(void* const* d_in, const int* in_sizes, int n_in,
                              void* d_out, int out_size) {
    const float* x  = (const float*)d_in[0];
    const float* y  = (const float*)d_in[1];
    const float* z  = (const float*)d_in[2];
    const float* W  = (const float*)d_in[3];
    const int*   Bi = (const int*)d_in[4];
    const float* Bw = (const float*)d_in[5];
    float* out = (float*)d_out;
    int NP = in_sizes[4] / 8;

    k_zero<<<1, 1>>>();
    k1<<<NW*NX, 256>>>(x, W);
    k2<<<NW*NX, 256>>>(y);
    k3<<<NW*NX*2, 256>>>(z);
    int tvN = M_TV*M_TV*NX;
    k_tv<<<(tvN + 255)/256, 256>>>();
    k_gather<<<(NP + 255)/256, 256>>>(Bi, Bw, out, NP);
    k_fin<<<1, 1>>>(out, out_size - 1);
}

// round 6
// speedup vs baseline: 1.5457x; 1.5457x over previous
#include <cuda_runtime.h>
#include <math.h>

#define NX 160
#define D  48
#define NW 3
#define N3 (NX*NX*NX)
#define M_TV 159
#define ZS_STRIDE 162   // row stride for zs[r][c]: even (LDS.64 align), mod 32 = 2 (low conflict)

// Scratch (device globals: allocation-free per harness rules)
__device__ float g_G1[NW*NX*D*D];     // [w][a][q][r]
__device__ float g_G2[NW*NX*NX*D];    // [w][a][b][r]
__device__ float4 g_G3[(size_t)N3];   // [n] = {g[w=0], g[w=1], g[w=2], 0}
__device__ double g_tv;

__global__ void k_zero() { g_tv = 0.0; }

// K1: G1[w][a][q][r] = sum_p x[a,p] * W[w,p,q,r]
__global__ void k1(const float* __restrict__ x, const float* __restrict__ W) {
    int blk = blockIdx.x;
    int w = blk / NX, a = blk % NX;
    __shared__ float xs[D];
    int t = threadIdx.x;
    if (t < D) xs[t] = x[a*D + t];
    __syncthreads();
    const float* Wp = W + (size_t)w*D*D*D;  // [p][q*48+r]
    float acc[9];
    #pragma unroll
    for (int j = 0; j < 9; j++) acc[j] = 0.f;
    for (int p = 0; p < D; p++) {
        float xv = xs[p];
        const float* row = Wp + p*(D*D);
        #pragma unroll
        for (int j = 0; j < 9; j++) acc[j] = fmaf(xv, row[t + 256*j], acc[j]);
    }
    float* outp = g_G1 + (size_t)blk*(D*D);
    #pragma unroll
    for (int j = 0; j < 9; j++) outp[t + 256*j] = acc[j];
}

// K2: G2[w][a][b][r] = sum_q y[b,q] * G1[w][a][q][r]
__global__ void k2(const float* __restrict__ y) {
    int blk = blockIdx.x;
    __shared__ float ys[NX][D];
    __shared__ float g1s[D][D];
    int t = threadIdx.x;
    const float* G1p = g_G1 + (size_t)blk*D*D;
    for (int i = t; i < NX*D; i += 256) ys[i/D][i%D] = y[i];
    for (int i = t; i < D*D; i += 256) g1s[i/D][i%D] = G1p[i];
    __syncthreads();
    int tx = t & 15, ty = t >> 4;
    float acc[10][3];
    #pragma unroll
    for (int jb = 0; jb < 10; jb++)
        #pragma unroll
        for (int jr = 0; jr < 3; jr++) acc[jb][jr] = 0.f;
    for (int q = 0; q < D; q++) {
        float yv[10], gv[3];
        #pragma unroll
        for (int jb = 0; jb < 10; jb++) yv[jb] = ys[ty + 16*jb][q];
        #pragma unroll
        for (int jr = 0; jr < 3; jr++) gv[jr] = g1s[q][tx + 16*jr];
        #pragma unroll
        for (int jb = 0; jb < 10; jb++)
            #pragma unroll
            for (int jr = 0; jr < 3; jr++)
                acc[jb][jr] = fmaf(yv[jb], gv[jr], acc[jb][jr]);
    }
    float* outp = g_G2 + (size_t)blk*NX*D;
    #pragma unroll
    for (int jb = 0; jb < 10; jb++)
        #pragma unroll
        for (int jr = 0; jr < 3; jr++)
            outp[(ty + 16*jb)*D + tx + 16*jr] = acc[jb][jr];
}

// K3: g[w,a,b,c] = sum_r G2[w][a][b][r] * z[c,r]  -> g_G3[n] = {w0,w1,w2,0}
// Block = (a, b-tile of 16). Threads (16 tx, 16 ty): b = bt*16+ty,
// c in pairs {2tx+32jc, +1}, jc<5, ALL 3 w per thread.
// Packed fp32x2 FMA: 15 f32x2 accumulators; z staged transposed zs[r][c].
__global__ void __launch_bounds__(256, 4) k3(const float* __restrict__ z) {
    int blk = blockIdx.x;
    int a = blk / 10, bt = blk % 10;
    __shared__ float zs[D * ZS_STRIDE];       // [r][c], stride 162 -> 31.1 KB
    __shared__ float g2s[NW][16][D];          // 9.2 KB
    int t = threadIdx.x;
    // zs fill: consecutive i -> consecutive r -> coalesced global read of z[c*48+r]
    for (int i = t; i < NX*D; i += 256) {
        int c = i / D, r = i % D;
        zs[r*ZS_STRIDE + c] = z[i];
    }
    // g2s fill: coalesced over r
    for (int i = t; i < NW*16*D; i += 256) {
        int w = i / (16*D);
        int rem = i % (16*D);
        int bl = rem / D, r = rem % D;
        g2s[w][bl][r] = g_G2[(((size_t)w*NX + a)*NX + bt*16 + bl)*D + r];
    }
    __syncthreads();
    int tx = t & 15, ty = t >> 4;

    unsigned long long acc[NW][5];
    #pragma unroll
    for (int w = 0; w < NW; w++)
        #pragma unroll
        for (int jc = 0; jc < 5; jc++) acc[w][jc] = 0ULL;

    int c_base = 2*tx;
    #pragma unroll 4
    for (int r = 0; r < D; r++) {
        // duplicate g2 scalars into both f32x2 lanes
        unsigned long long wp[NW];
        #pragma unroll
        for (int w = 0; w < NW; w++) {
            unsigned int gb = __float_as_uint(g2s[w][ty][r]);
            asm("mov.b64 %0, {%1, %1};" : "=l"(wp[w]) : "r"(gb));
        }
        const float* zrow = &zs[r*ZS_STRIDE];
        #pragma unroll
        for (int jc = 0; jc < 5; jc++) {
            unsigned long long zp =
                *reinterpret_cast<const unsigned long long*>(&zrow[c_base + 32*jc]);
            #pragma unroll
            for (int w = 0; w < NW; w++)
                asm("fma.rn.f32x2 %0, %1, %2, %0;" : "+l"(acc[w][jc]) : "l"(zp), "l"(wp[w]));
        }
    }

    int b = bt*16 + ty;
    size_t rowbase = ((size_t)a*NX + b)*NX;
    #pragma unroll
    for (int jc = 0; jc < 5; jc++) {
        int c0 = c_base + 32*jc;
        unsigned int lo[NW], hi[NW];
        #pragma unroll
        for (int w = 0; w < NW; w++)
            asm("mov.b64 {%0, %1}, %2;" : "=r"(lo[w]), "=r"(hi[w]) : "l"(acc[w][jc]));
        float4 f0, f1;
        f0.x = __uint_as_float(lo[0]); f0.y = __uint_as_float(lo[1]);
        f0.z = __uint_as_float(lo[2]); f0.w = 0.f;
        f1.x = __uint_as_float(hi[0]); f1.y = __uint_as_float(hi[1]);
        f1.z = __uint_as_float(hi[2]); f1.w = 0.f;
        g_G3[rowbase + c0]     = f0;
        g_G3[rowbase + c0 + 1] = f1;
    }
}

// TV: sum over w,a,b,c<159 of sqrt(eps + dc^2 + db^2 + da^2)
__global__ void k_tv() {
    int idx = blockIdx.x*blockDim.x + threadIdx.x;
    float val = 0.f;
    if (idx < M_TV*M_TV*NX) {
        int c = idx % NX;
        int tmp = idx / NX;
        int b = tmp % M_TV;
        int a = tmp / M_TV;
        if (c < M_TV) {
            size_t n = ((size_t)a*NX + b)*NX + c;
            float4 v0 = __ldg(&g_G3[n]);
            float4 vc = __ldg(&g_G3[n + 1]);
            float4 vb = __ldg(&g_G3[n + NX]);
            float4 va = __ldg(&g_G3[n + (size_t)NX*NX]);
            float dc, db, da;
            dc = vc.x - v0.x; db = vb.x - v0.x; da = va.x - v0.x;
            val += sqrtf(1e-5f + dc*dc + db*db + da*da);
            dc = vc.y - v0.y; db = vb.y - v0.y; da = va.y - v0.y;
            val += sqrtf(1e-5f + dc*dc + db*db + da*da);
            dc = vc.z - v0.z; db = vb.z - v0.z; da = va.z - v0.z;
            val += sqrtf(1e-5f + dc*dc + db*db + da*da);
        }
    }
    #pragma unroll
    for (int o = 16; o > 0; o >>= 1) val += __shfl_down_sync(0xffffffffu, val, o);
    __shared__ float warp_sums[8];
    int t = threadIdx.x;
    if ((t & 31) == 0) warp_sums[t >> 5] = val;
    __syncthreads();
    if (t == 0) {
        float s = 0.f;
        #pragma unroll
        for (int i = 0; i < 8; i++) s += warp_sums[i];
        atomicAdd(&g_tv, (double)s);
    }
}

__global__ void k_fin(float* __restrict__ out, int pos) {
    double denom = (double)M_TV * M_TV * M_TV;
    out[pos] = (float)(g_tv / denom);  // SCALING = 1.0
}

// Gather: out[i][w] = sum_k B_w[i,k] * g3[B_idx[i,k]].{x,y,z}
// One aligned LDG.128 per tap: exactly 1 L2 sector each; MLP 8.
__global__ void k_gather(const int* __restrict__ B_idx, const float* __restrict__ B_w,
                         float* __restrict__ out, int NP) {
    int i = blockIdx.x*blockDim.x + threadIdx.x;
    if (i >= NP) return;
    const int4*   bi = (const int4*)(B_idx + (size_t)i*8);
    const float4* bw = (const float4*)(B_w + (size_t)i*8);
    int4 i0 = bi[0], i1 = bi[1];
    float4 w0 = bw[0], w1 = bw[1];
    int   idxs[8] = {i0.x, i0.y, i0.z, i0.w, i1.x, i1.y, i1.z, i1.w};
    float ws[8]   = {w0.x, w0.y, w0.z, w0.w, w1.x, w1.y, w1.z, w1.w};
    float4 v[8];
    #pragma unroll
    for (int k = 0; k < 8; k++) v[k] = __ldg(&g_G3[(size_t)idxs[k]]);
    float a0 = 0.f, a1 = 0.f, a2 = 0.f;
    #pragma unroll
    for (int k = 0; k < 8; k++) {
        float wk = ws[k];
        a0 = fmaf(wk, v[k].x, a0);
        a1 = fmaf(wk, v[k].y, a1);
        a2 = fmaf(wk, v[k].z, a2);
    }
    size_t o = (size_t)i*3;
    out[o + 0] = a0;
    out[o + 1] = a1;
    out[o + 2] = a2;
}

extern "C" void kernel_launch(void* const* d_in, const int* in_sizes, int n_in,
                              void* d_out, int out_size) {
    const float* x  = (const float*)d_in[0];
    const float* y  = (const float*)d_in[1];
    const float* z  = (const float*)d_in[2];
    const float* W  = (const float*)d_in[3];
    const int*   Bi = (const int*)d_in[4];
    const float* Bw = (const float*)d_in[5];
    float* out = (float*)d_out;
    int NP = in_sizes[4] / 8;

    k_zero<<<1, 1>>>();
    k1<<<NW*NX, 256>>>(x, W);
    k2<<<NW*NX, 256>>>(y);
    k3<<<NX*10, 256>>>(z);
    int tvN = M_TV*M_TV*NX;
    k_tv<<<(tvN + 255)/256, 256>>>();
    k_gather<<<(NP + 255)/256, 256>>>(Bi, Bw, out, NP);
    k_fin<<<1, 1>>>(out, out_size - 1);
}

// round 7
// speedup vs baseline: 1.5946x; 1.0317x over previous
#include <cuda_runtime.h>
#include <math.h>

#define NX 160
#define D  48
#define NW 3
#define N3 (NX*NX*NX)
#define M_TV 159
#define ZS_STRIDE 162   // row stride for zs[r][c]: even (LDS.64 align), mod 32 = 2 (low conflict)

// Scratch (device globals: allocation-free per harness rules)
__device__ float g_G1[NW*NX*D*D];     // [w][a][q][r]
__device__ float g_G2[NW*NX*NX*D];    // [w][a][b][r]
__device__ float4 g_G3[(size_t)N3];   // [n] = {g[w=0], g[w=1], g[w=2], 0}
__device__ double g_tv;

__global__ void k_zero() { g_tv = 0.0; }

// K1: G1[w][a][q][r] = sum_p x[a,p] * W[w,p,q,r]
__global__ void k1(const float* __restrict__ x, const float* __restrict__ W) {
    int blk = blockIdx.x;
    int w = blk / NX, a = blk % NX;
    __shared__ float xs[D];
    int t = threadIdx.x;
    if (t < D) xs[t] = x[a*D + t];
    __syncthreads();
    const float* Wp = W + (size_t)w*D*D*D;  // [p][q*48+r]
    float acc[9];
    #pragma unroll
    for (int j = 0; j < 9; j++) acc[j] = 0.f;
    for (int p = 0; p < D; p++) {
        float xv = xs[p];
        const float* row = Wp + p*(D*D);
        #pragma unroll
        for (int j = 0; j < 9; j++) acc[j] = fmaf(xv, row[t + 256*j], acc[j]);
    }
    float* outp = g_G1 + (size_t)blk*(D*D);
    #pragma unroll
    for (int j = 0; j < 9; j++) outp[t + 256*j] = acc[j];
}

// K2: G2[w][a][b][r] = sum_q y[b,q] * G1[w][a][q][r]
__global__ void k2(const float* __restrict__ y) {
    int blk = blockIdx.x;
    __shared__ float ys[NX][D];
    __shared__ float g1s[D][D];
    int t = threadIdx.x;
    const float* G1p = g_G1 + (size_t)blk*D*D;
    for (int i = t; i < NX*D; i += 256) ys[i/D][i%D] = y[i];
    for (int i = t; i < D*D; i += 256) g1s[i/D][i%D] = G1p[i];
    __syncthreads();
    int tx = t & 15, ty = t >> 4;
    float acc[10][3];
    #pragma unroll
    for (int jb = 0; jb < 10; jb++)
        #pragma unroll
        for (int jr = 0; jr < 3; jr++) acc[jb][jr] = 0.f;
    for (int q = 0; q < D; q++) {
        float yv[10], gv[3];
        #pragma unroll
        for (int jb = 0; jb < 10; jb++) yv[jb] = ys[ty + 16*jb][q];
        #pragma unroll
        for (int jr = 0; jr < 3; jr++) gv[jr] = g1s[q][tx + 16*jr];
        #pragma unroll
        for (int jb = 0; jb < 10; jb++)
            #pragma unroll
            for (int jr = 0; jr < 3; jr++)
                acc[jb][jr] = fmaf(yv[jb], gv[jr], acc[jb][jr]);
    }
    float* outp = g_G2 + (size_t)blk*NX*D;
    #pragma unroll
    for (int jb = 0; jb < 10; jb++)
        #pragma unroll
        for (int jr = 0; jr < 3; jr++)
            outp[(ty + 16*jb)*D + tx + 16*jr] = acc[jb][jr];
}

// K3: g[w,a,b,c] = sum_r G2[w][a][b][r] * z[c,r]  -> g_G3[n] = {w0,w1,w2,0}
// Packed fp32x2 FMA, all 3 w per thread, STG.128 stores.
__global__ void __launch_bounds__(256, 4) k3(const float* __restrict__ z) {
    int blk = blockIdx.x;
    int a = blk / 10, bt = blk % 10;
    __shared__ float zs[D * ZS_STRIDE];       // [r][c], 31.1 KB
    __shared__ float g2s[NW][16][D];          // 9.2 KB
    int t = threadIdx.x;
    for (int i = t; i < NX*D; i += 256) {
        int c = i / D, r = i % D;
        zs[r*ZS_STRIDE + c] = z[i];
    }
    for (int i = t; i < NW*16*D; i += 256) {
        int w = i / (16*D);
        int rem = i % (16*D);
        int bl = rem / D, r = rem % D;
        g2s[w][bl][r] = g_G2[(((size_t)w*NX + a)*NX + bt*16 + bl)*D + r];
    }
    __syncthreads();
    int tx = t & 15, ty = t >> 4;

    unsigned long long acc[NW][5];
    #pragma unroll
    for (int w = 0; w < NW; w++)
        #pragma unroll
        for (int jc = 0; jc < 5; jc++) acc[w][jc] = 0ULL;

    int c_base = 2*tx;
    #pragma unroll 4
    for (int r = 0; r < D; r++) {
        unsigned long long wp[NW];
        #pragma unroll
        for (int w = 0; w < NW; w++) {
            unsigned int gb = __float_as_uint(g2s[w][ty][r]);
            asm("mov.b64 %0, {%1, %1};" : "=l"(wp[w]) : "r"(gb));
        }
        const float* zrow = &zs[r*ZS_STRIDE];
        #pragma unroll
        for (int jc = 0; jc < 5; jc++) {
            unsigned long long zp =
                *reinterpret_cast<const unsigned long long*>(&zrow[c_base + 32*jc]);
            #pragma unroll
            for (int w = 0; w < NW; w++)
                asm("fma.rn.f32x2 %0, %1, %2, %0;" : "+l"(acc[w][jc]) : "l"(zp), "l"(wp[w]));
        }
    }

    int b = bt*16 + ty;
    size_t rowbase = ((size_t)a*NX + b)*NX;
    #pragma unroll
    for (int jc = 0; jc < 5; jc++) {
        int c0 = c_base + 32*jc;
        unsigned int lo[NW], hi[NW];
        #pragma unroll
        for (int w = 0; w < NW; w++)
            asm("mov.b64 {%0, %1}, %2;" : "=r"(lo[w]), "=r"(hi[w]) : "l"(acc[w][jc]));
        float4 f0, f1;
        f0.x = __uint_as_float(lo[0]); f0.y = __uint_as_float(lo[1]);
        f0.z = __uint_as_float(lo[2]); f0.w = 0.f;
        f1.x = __uint_as_float(hi[0]); f1.y = __uint_as_float(hi[1]);
        f1.z = __uint_as_float(hi[2]); f1.w = 0.f;
        g_G3[rowbase + c0]     = f0;
        g_G3[rowbase + c0 + 1] = f1;
    }
}

// TV: sum over w,a,b,c<159 of sqrt(eps + dc^2 + db^2 + da^2)
__global__ void k_tv() {
    int idx = blockIdx.x*blockDim.x + threadIdx.x;
    float val = 0.f;
    if (idx < M_TV*M_TV*NX) {
        int c = idx % NX;
        int tmp = idx / NX;
        int b = tmp % M_TV;
        int a = tmp / M_TV;
        if (c < M_TV) {
            size_t n = ((size_t)a*NX + b)*NX + c;
            float4 v0 = __ldg(&g_G3[n]);
            float4 vc = __ldg(&g_G3[n + 1]);
            float4 vb = __ldg(&g_G3[n + NX]);
            float4 va = __ldg(&g_G3[n + (size_t)NX*NX]);
            float dc, db, da;
            dc = vc.x - v0.x; db = vb.x - v0.x; da = va.x - v0.x;
            val += sqrtf(1e-5f + dc*dc + db*db + da*da);
            dc = vc.y - v0.y; db = vb.y - v0.y; da = va.y - v0.y;
            val += sqrtf(1e-5f + dc*dc + db*db + da*da);
            dc = vc.z - v0.z; db = vb.z - v0.z; da = va.z - v0.z;
            val += sqrtf(1e-5f + dc*dc + db*db + da*da);
        }
    }
    #pragma unroll
    for (int o = 16; o > 0; o >>= 1) val += __shfl_down_sync(0xffffffffu, val, o);
    __shared__ float warp_sums[8];
    int t = threadIdx.x;
    if ((t & 31) == 0) warp_sums[t >> 5] = val;
    __syncthreads();
    if (t == 0) {
        float s = 0.f;
        #pragma unroll
        for (int i = 0; i < 8; i++) s += warp_sums[i];
        atomicAdd(&g_tv, (double)s);
    }
}

__global__ void k_fin(float* __restrict__ out, int pos) {
    double denom = (double)M_TV * M_TV * M_TV;
    out[pos] = (float)(g_tv / denom);  // SCALING = 1.0
}

// Gather, quad-per-point: lanes 4i..4i+3 handle point i; lane l reads the
// single float G3[idx*4+l] (4 B). Quad shares one 128-B line per tap ->
// warp LDG.32 touches 8 distinct lines (8 wf) instead of LDG.128's 32
// within-instruction replays. Idx/weights loaded redundantly per quad
// (same lines -> L1 broadcast). Lane 3 computes on the zero pad, stores nothing.
__global__ void k_gather(const int* __restrict__ B_idx, const float* __restrict__ B_w,
                         float* __restrict__ out, int NP) {
    int tid = blockIdx.x*blockDim.x + threadIdx.x;
    int i  = tid >> 2;
    int lw = tid & 3;
    if (i >= NP) return;
    const int4*   bi = (const int4*)(B_idx + (size_t)i*8);
    const float4* bw = (const float4*)(B_w + (size_t)i*8);
    int4 i0 = bi[0], i1 = bi[1];
    float4 w0 = bw[0], w1 = bw[1];
    int   idxs[8] = {i0.x, i0.y, i0.z, i0.w, i1.x, i1.y, i1.z, i1.w};
    float ws[8]   = {w0.x, w0.y, w0.z, w0.w, w1.x, w1.y, w1.z, w1.w};
    const float* G3f = (const float*)g_G3;
    float v[8];
    #pragma unroll
    for (int k = 0; k < 8; k++)
        v[k] = __ldg(G3f + (((size_t)idxs[k]) << 2) + lw);
    float acc = 0.f;
    #pragma unroll
    for (int k = 0; k < 8; k++) acc = fmaf(ws[k], v[k], acc);
    if (lw < 3) out[(size_t)i*3 + lw] = acc;
}

extern "C" void kernel_launch(void* const* d_in, const int* in_sizes, int n_in,
                              void* d_out, int out_size) {
    const float* x  = (const float*)d_in[0];
    const float* y  = (const float*)d_in[1];
    const float* z  = (const float*)d_in[2];
    const float* W  = (const float*)d_in[3];
    const int*   Bi = (const int*)d_in[4];
    const float* Bw = (const float*)d_in[5];
    float* out = (float*)d_out;
    int NP = in_sizes[4] / 8;

    k_zero<<<1, 1>>>();
    k1<<<NW*NX, 256>>>(x, W);
    k2<<<NW*NX, 256>>>(y);
    k3<<<NX*10, 256>>>(z);
    int tvN = M_TV*M_TV*NX;
    k_tv<<<(tvN + 255)/256, 256>>>();
    long long nthreads = (long long)NP * 4;
    k_gather<<<(int)((nthreads + 255)/256), 256>>>(Bi, Bw, out, NP);
    k_fin<<<1, 1>>>(out, out_size - 1);
}